// round 10
// baseline (speedup 1.0000x reference)
#include <cuda_runtime.h>
#include <cuda_bf16.h>
#include <cstdint>

// ---------------- problem constants ----------------
#define NB   2048
#define NTT  1024
#define NF   10
#define NROWS (NB * NTT)
#define TILE_ROWS 128
#define NTILES (NROWS / TILE_ROWS)   // 16384
#define GRID_PERSIST 148
#define THREADS 512

// scan chunking
#define CHUNK 64
#define NCH (NTT / CHUNK)            // 16

// ---------------- smem layout (bytes) ----------------
#define MAT_STRIDE 272               // 128 bf16 cols padded to 17*16B -> LDSM conflict-free
#define MAT_BYTES  (128 * MAT_STRIDE)

#define OFF_W1   0                        // 1152 floats = 4608 B
#define OFF_B1   4608
#define OFF_B2   5120
#define OFF_W3   5632                     // 256 floats = 1024 B
#define OFF_RED  6656                     // 128 float2 = 1024 B
#define OFF_A    7680                     // [2 bufs][hi,lo] x MAT_BYTES
#define OFF_BHI  (OFF_A + 4 * MAT_BYTES)  // 146944
#define OFF_BLO  (OFF_BHI + MAT_BYTES)
#define SMEM_BYTES (OFF_BLO + MAT_BYTES)  // 216576

// ---------------- PTX helpers ----------------
__device__ __forceinline__ uint32_t smem_u32(const void* p) {
    uint32_t a;
    asm("{ .reg .u64 t; cvta.to.shared.u64 t, %1; cvt.u32.u64 %0, t; }" : "=r"(a) : "l"(p));
    return a;
}
__device__ __forceinline__ void ldm_x4(uint32_t* r, uint32_t addr) {
    asm volatile("ldmatrix.sync.aligned.m8n8.x4.shared.b16 {%0,%1,%2,%3}, [%4];"
                 : "=r"(r[0]), "=r"(r[1]), "=r"(r[2]), "=r"(r[3]) : "r"(addr));
}
__device__ __forceinline__ void mma_bf16(float* d, const uint32_t* a, const uint32_t* b) {
    asm volatile(
        "mma.sync.aligned.m16n8k16.row.col.f32.bf16.bf16.f32 "
        "{%0,%1,%2,%3}, {%4,%5,%6,%7}, {%8,%9}, {%0,%1,%2,%3};"
        : "+f"(d[0]), "+f"(d[1]), "+f"(d[2]), "+f"(d[3])
        : "r"(a[0]), "r"(a[1]), "r"(a[2]), "r"(a[3]), "r"(b[0]), "r"(b[1]));
}

// ---------------- math helpers ----------------
__device__ __forceinline__ float fast_tanh(float x) {
    float e = __expf(2.0f * x);
    return 1.0f - __fdividef(2.0f, e + 1.0f);
}
// exact RK4 step, same arithmetic as reference
__device__ __forceinline__ void rk4_step(float& Ca, float& Cb, float u) {
    const float it = 0.1f, dlt = 0.1f;
    float k1a = (u - Ca) * it - Ca;
    float k1b = Ca - Cb * it;
    float xa = Ca + 0.5f * dlt * k1a, xb = Cb + 0.5f * dlt * k1b;
    float k2a = (u - xa) * it - xa;
    float k2b = xa - xb * it;
    xa = Ca + 0.5f * dlt * k2a; xb = Cb + 0.5f * dlt * k2b;
    float k3a = (u - xa) * it - xa;
    float k3b = xa - xb * it;
    xa = Ca + dlt * k3a; xb = Cb + dlt * k3b;
    float k4a = (u - xa) * it - xa;
    float k4b = xa - xb * it;
    Ca += (dlt / 6.0f) * (k1a + 2.0f * k2a + 2.0f * k3a + k4a);
    Cb += (dlt / 6.0f) * (k1b + 2.0f * k2b + 2.0f * k3b + k4b);
}

// ---------------- scan scratch ----------------
__device__ float g_v[NB * NCH * 2];
__device__ float g_s[NB * NCH * 2];

__global__ void scan_p1(const float* __restrict__ inputs) {
    int idx = blockIdx.x * blockDim.x + threadIdx.x;
    if (idx >= NB * NCH) return;
    int b = idx >> 4, c = idx & 15;
    const float* up = inputs + ((size_t)b * NTT + c * CHUNK) * NF;
    float Ca = 0.f, Cb = 0.f;
    for (int t0 = 0; t0 < CHUNK; t0 += 8) {
        float uu[8];
        #pragma unroll
        for (int j = 0; j < 8; ++j) uu[j] = up[(size_t)(t0 + j) * NF];
        #pragma unroll
        for (int j = 0; j < 8; ++j) rk4_step(Ca, Cb, uu[j]);
    }
    g_v[idx * 2] = Ca; g_v[idx * 2 + 1] = Cb;
}

__global__ void scan_p2(const float* __restrict__ x0) {
    int b = blockIdx.x * blockDim.x + threadIdx.x;
    if (b >= NB) return;
    float m00 = 1.f, m10 = 0.f;
    for (int t = 0; t < CHUNK; ++t) rk4_step(m00, m10, 0.f);
    float m01 = 0.f, m11 = 1.f;
    for (int t = 0; t < CHUNK; ++t) rk4_step(m01, m11, 0.f);
    float Ca = x0[2 * b], Cb = x0[2 * b + 1];
    #pragma unroll
    for (int c = 0; c < NCH; ++c) {
        int idx = b * NCH + c;
        g_s[idx * 2] = Ca; g_s[idx * 2 + 1] = Cb;
        float na = fmaf(m00, Ca, fmaf(m01, Cb, g_v[idx * 2]));
        float nb = fmaf(m10, Ca, fmaf(m11, Cb, g_v[idx * 2 + 1]));
        Ca = na; Cb = nb;
    }
}

__global__ void scan_p3(const float* __restrict__ inputs, float* __restrict__ out) {
    int idx = blockIdx.x * blockDim.x + threadIdx.x;
    if (idx >= NB * NCH) return;
    int b = idx >> 4, c = idx & 15;
    float Ca = g_s[idx * 2], Cb = g_s[idx * 2 + 1];
    const float* up = inputs + ((size_t)b * NTT + c * CHUNK) * NF;
    float2* op = (float2*)(out + ((size_t)b * NTT + c * CHUNK) * 2);
    for (int t0 = 0; t0 < CHUNK; t0 += 8) {
        float uu[8];
        #pragma unroll
        for (int j = 0; j < 8; ++j) uu[j] = up[(size_t)(t0 + j) * NF];
        #pragma unroll
        for (int j = 0; j < 8; ++j) {
            op[t0 + j] = make_float2(Ca, Cb);
            rk4_step(Ca, Cb, uu[j]);
        }
    }
}

// ============================================================================
// Persistent fused MLP, homogeneous software pipeline.
// Each region: ALL 16 warps produce A(tile j+1) into buf[(j+1)&1], then
// consume A(tile j) from buf[j&1] (ldmatrix + 3-pass bf16 mma + epilogue).
// Two __syncthreads per tile (epilogue reduce + region boundary).
// ============================================================================
__device__ __forceinline__ void produce_tile(
    const float* __restrict__ inputs, char* smem, int tile, int buf,
    int row, int jq, const float4* W1v, const float4* b1v) {
    // direct LDG of this row's 9 features (8B-aligned float2s)
    const float* xr = inputs + ((size_t)tile * TILE_ROWS + row) * NF;
    float2 p0 = *(const float2*)(xr);
    float2 p1 = *(const float2*)(xr + 2);
    float2 p2 = *(const float2*)(xr + 4);
    float2 p3 = *(const float2*)(xr + 6);
    float2 p4 = *(const float2*)(xr + 8);
    float x[9] = {p0.y, p1.x, p1.y, p2.x, p2.y, p3.x, p3.y, p4.x, p4.y};

    char* abhi = smem + OFF_A + buf * (2 * MAT_BYTES);
    char* ablo = abhi + MAT_BYTES;

    #pragma unroll
    for (int q = 0; q < 8; ++q) {
        const int j4 = jq * 8 + q;
        float4 a = b1v[j4];
        #pragma unroll
        for (int k = 0; k < 9; ++k) {
            float4 w = W1v[k * 32 + j4];      // uniform within warp
            a.x = fmaf(x[k], w.x, a.x);
            a.y = fmaf(x[k], w.y, a.y);
            a.z = fmaf(x[k], w.z, a.z);
            a.w = fmaf(x[k], w.w, a.w);
        }
        float t0 = fast_tanh(a.x), t1 = fast_tanh(a.y);
        float t2 = fast_tanh(a.z), t3 = fast_tanh(a.w);
        __nv_bfloat16 h0 = __float2bfloat16(t0), h1 = __float2bfloat16(t1);
        __nv_bfloat16 h2 = __float2bfloat16(t2), h3 = __float2bfloat16(t3);
        __nv_bfloat16 l0 = __float2bfloat16(t0 - __bfloat162float(h0));
        __nv_bfloat16 l1 = __float2bfloat16(t1 - __bfloat162float(h1));
        __nv_bfloat16 l2 = __float2bfloat16(t2 - __bfloat162float(h2));
        __nv_bfloat16 l3 = __float2bfloat16(t3 - __bfloat162float(h3));
        uint2 hv, lv;
        hv.x = (uint32_t)__bfloat16_as_ushort(h0) | ((uint32_t)__bfloat16_as_ushort(h1) << 16);
        hv.y = (uint32_t)__bfloat16_as_ushort(h2) | ((uint32_t)__bfloat16_as_ushort(h3) << 16);
        lv.x = (uint32_t)__bfloat16_as_ushort(l0) | ((uint32_t)__bfloat16_as_ushort(l1) << 16);
        lv.y = (uint32_t)__bfloat16_as_ushort(l2) | ((uint32_t)__bfloat16_as_ushort(l3) << 16);
        const uint32_t byte = (uint32_t)(row * MAT_STRIDE + jq * 64 + q * 8);
        *(uint2*)(abhi + byte) = hv;
        *(uint2*)(ablo + byte) = lv;
    }
}

__global__ void __launch_bounds__(THREADS, 1)
mlp_kernel(const float* __restrict__ inputs,
           const float* __restrict__ W1,
           const float* __restrict__ b1,
           const float* __restrict__ W2,
           const float* __restrict__ b2,
           const float* __restrict__ W3,
           float* __restrict__ out) {
    extern __shared__ char smem[];
    const uint32_t smb = smem_u32(smem);
    const int tid  = threadIdx.x;
    const int wid  = tid >> 5;
    const int lane = tid & 31;

    // ---- one-time weight staging ----
    {
        for (int i = tid; i < 16384; i += THREADS) {
            int k = i >> 7, n = i & 127;
            float w = W2[i];                           // coalesced
            __nv_bfloat16 hb = __float2bfloat16(w);
            __nv_bfloat16 lb = __float2bfloat16(w - __bfloat162float(hb));
            uint32_t byte = (uint32_t)(n * MAT_STRIDE + k * 2);
            *(__nv_bfloat16*)(smem + OFF_BHI + byte) = hb;
            *(__nv_bfloat16*)(smem + OFF_BLO + byte) = lb;
        }
        float4* s1 = (float4*)(smem + OFF_W1);
        const float4* g1 = (const float4*)W1;
        for (int i = tid; i < 288; i += THREADS) s1[i] = g1[i];
        if (tid < 32)       ((float4*)(smem + OFF_B1))[tid]       = ((const float4*)b1)[tid];
        else if (tid < 64)  ((float4*)(smem + OFF_B2))[tid - 32]  = ((const float4*)b2)[tid - 32];
        else if (tid < 128) ((float4*)(smem + OFF_W3))[tid - 64]  = ((const float4*)W3)[tid - 64];
    }
    __syncthreads();

    // produce mapping: row = tid&127, quarter jq = tid>>7 (32 cols)
    const int row = tid & 127;
    const int jq  = tid >> 7;
    // consume mapping: band = wid&7 (16 rows), half = wid>>3 (64 cols)
    const int band = wid & 7;
    const int half = wid >> 3;
    const int R0 = band * 16;
    const int N0 = half * 64;
    const int aRow = lane & 15;
    const int aKh  = (lane >> 4) * 16;
    const int bRow = ((lane >> 4) & 1) * 8 + (lane & 7);
    const int bKh  = ((lane >> 3) & 1) * 16;

    const float4* W1v = (const float4*)(smem + OFF_W1);
    const float4* b1v = (const float4*)(smem + OFF_B1);
    const float*  b2s = (const float*)(smem + OFF_B2);
    const float*  W3s = (const float*)(smem + OFF_W3);
    float2* red = (float2*)(smem + OFF_RED);

    // ---- prologue: produce first tile into buf 0 ----
    produce_tile(inputs, smem, blockIdx.x, 0, row, jq, W1v, b1v);
    __syncthreads();

    int i = 1;
    for (int tc = blockIdx.x; tc < NTILES; tc += GRID_PERSIST, ++i) {
        const int pb = i & 1;         // buffer being produced this region
        const int cb = pb ^ 1;        // buffer being consumed this region

        // ---- produce next tile (overlaps with consume below via warp drift) ----
        const int tp = tc + GRID_PERSIST;
        if (tp < NTILES) produce_tile(inputs, smem, tp, pb, row, jq, W1v, b1v);

        // ---- consume current tile: 3-pass bf16 mma, 16x64 per warp ----
        const uint32_t ahiB = smb + OFF_A + (uint32_t)(cb * (2 * MAT_BYTES));
        const uint32_t aloB = ahiB + MAT_BYTES;

        float acc[8][4];
        #pragma unroll
        for (int nt = 0; nt < 8; ++nt)
            #pragma unroll
            for (int c = 0; c < 4; ++c) acc[nt][c] = 0.0f;

        #pragma unroll
        for (int ks = 0; ks < 8; ++ks) {
            const int K0 = ks * 32;
            const uint32_t aoff = (uint32_t)((R0 + aRow) * MAT_STRIDE + K0 + aKh);
            uint32_t ahi[4], alo[4];
            ldm_x4(ahi, ahiB + aoff);
            ldm_x4(alo, aloB + aoff);
            uint32_t bh[8][2], bl[8][2];
            #pragma unroll
            for (int np = 0; np < 4; ++np) {
                const uint32_t boff =
                    (uint32_t)((N0 + np * 16 + bRow) * MAT_STRIDE + K0 + bKh);
                uint32_t r4[4];
                ldm_x4(r4, smb + OFF_BHI + boff);
                bh[2 * np][0] = r4[0]; bh[2 * np][1] = r4[1];
                bh[2 * np + 1][0] = r4[2]; bh[2 * np + 1][1] = r4[3];
                ldm_x4(r4, smb + OFF_BLO + boff);
                bl[2 * np][0] = r4[0]; bl[2 * np][1] = r4[1];
                bl[2 * np + 1][0] = r4[2]; bl[2 * np + 1][1] = r4[3];
            }
            #pragma unroll
            for (int nt = 0; nt < 8; ++nt) {
                float* d = acc[nt];
                mma_bf16(d, ahi, bh[nt]);
                mma_bf16(d, ahi, bl[nt]);
                mma_bf16(d, alo, bh[nt]);
            }
        }

        // ---- epilogue: tanh(acc + b2) @ W3, warp-local partial over 64 cols ----
        float rr[2][2];
        rr[0][0] = rr[0][1] = rr[1][0] = rr[1][1] = 0.f;
        #pragma unroll
        for (int nt = 0; nt < 8; ++nt) {
            const int c0 = N0 + nt * 8 + 2 * (lane & 3);
            const float w300 = W3s[2 * c0],     w301 = W3s[2 * c0 + 1];
            const float w310 = W3s[2 * c0 + 2], w311 = W3s[2 * c0 + 3];
            const float bb0 = b2s[c0], bb1 = b2s[c0 + 1];
            float h;
            h = fast_tanh(acc[nt][0] + bb0);
            rr[0][0] = fmaf(h, w300, rr[0][0]);
            rr[0][1] = fmaf(h, w301, rr[0][1]);
            h = fast_tanh(acc[nt][1] + bb1);
            rr[0][0] = fmaf(h, w310, rr[0][0]);
            rr[0][1] = fmaf(h, w311, rr[0][1]);
            h = fast_tanh(acc[nt][2] + bb0);
            rr[1][0] = fmaf(h, w300, rr[1][0]);
            rr[1][1] = fmaf(h, w301, rr[1][1]);
            h = fast_tanh(acc[nt][3] + bb1);
            rr[1][0] = fmaf(h, w310, rr[1][0]);
            rr[1][1] = fmaf(h, w311, rr[1][1]);
        }
        #pragma unroll
        for (int hf = 0; hf < 2; ++hf)
            #pragma unroll
            for (int c = 0; c < 2; ++c) {
                float v = rr[hf][c];
                v += __shfl_xor_sync(0xffffffffu, v, 1);
                v += __shfl_xor_sync(0xffffffffu, v, 2);
                rr[hf][c] = v;
            }

        // half 1 publishes its partial; half 0 combines and stores
        if (half == 1 && (lane & 3) == 0) {
            #pragma unroll
            for (int hf = 0; hf < 2; ++hf) {
                const int r = R0 + hf * 8 + (lane >> 2);
                red[r] = make_float2(rr[hf][0], rr[hf][1]);
            }
        }
        __syncthreads();   // red visible; also all consume-reads of cb done
        if (half == 0 && (lane & 3) == 0) {
            #pragma unroll
            for (int hf = 0; hf < 2; ++hf) {
                const int r = R0 + hf * 8 + (lane >> 2);
                const float2 p = red[r];
                const size_t o = ((size_t)tc * TILE_ROWS + r) * 2;
                float2 v = *(float2*)(out + o);     // xG from scan
                v.x += rr[hf][0] + p.x;
                v.y += rr[hf][1] + p.y;
                *(float2*)(out + o) = v;
            }
        }
        __syncthreads();   // region boundary: red reusable, buffers swap
    }
}

// ============================================================================
extern "C" void kernel_launch(void* const* d_in, const int* in_sizes, int n_in,
                              void* d_out, int out_size) {
    const float* inputs = (const float*)d_in[0];
    const float* x0     = (const float*)d_in[1];
    const float* W1     = (const float*)d_in[2];
    const float* b1     = (const float*)d_in[3];
    const float* W2     = (const float*)d_in[4];
    const float* b2     = (const float*)d_in[5];
    const float* W3     = (const float*)d_in[6];
    float* out = (float*)d_out;

    cudaFuncSetAttribute(mlp_kernel,
                         cudaFuncAttributeMaxDynamicSharedMemorySize, SMEM_BYTES);

    scan_p1<<<(NB * NCH) / 256, 256>>>(inputs);
    scan_p2<<<NB / 256, 256>>>(x0);
    scan_p3<<<(NB * NCH) / 256, 256>>>(inputs, out);
    mlp_kernel<<<GRID_PERSIST, THREADS, SMEM_BYTES>>>(inputs, W1, b1, W2, b2, W3, out);
}